// round 3
// baseline (speedup 1.0000x reference)
#include <cuda_runtime.h>
#include <cstdint>
#include <math.h>

#define T_TOKENS 4096
#define DMODEL   1024
#define DFF      2048
#define NEXP     8
#define KCH      32

// smem layout (dynamic): A frags 16KB | B frags 32KB | tok 512B | gate 512B
#define OFF_A    0
#define OFF_B    16384
#define OFF_TOK  49152
#define OFF_GATE 49664
#define SMEM_SZ  50176

// ---------------- scratch (device globals; no runtime alloc) ----------------
__device__ int   g_counts[NEXP];
__device__ int   g_elist[NEXP][T_TOKENS];
__device__ float g_egate[NEXP][T_TOKENS];
__device__ float g_act[(size_t)NEXP * T_TOKENS * DFF];

// ---------------- helpers ----------------
__device__ __forceinline__ uint32_t f2tf(float x) {
    uint32_t r; asm("cvt.rna.tf32.f32 %0, %1;" : "=r"(r) : "f"(x)); return r;
}
__device__ __forceinline__ void mma8(float* d, const uint32_t* a, const uint32_t* b) {
    asm volatile(
        "mma.sync.aligned.m16n8k8.row.col.f32.tf32.tf32.f32 "
        "{%0,%1,%2,%3}, {%4,%5,%6,%7}, {%8,%9}, {%0,%1,%2,%3};\n"
        : "+f"(d[0]), "+f"(d[1]), "+f"(d[2]), "+f"(d[3])
        : "r"(a[0]), "r"(a[1]), "r"(a[2]), "r"(a[3]), "r"(b[0]), "r"(b[1]));
}

// fragment-major addressing
// A vector16B at: ((wm*4+ks)*4+mt)*512 + (g*4 + (c ^ ((g>>1)&3)))*16 + (sub+2q)*4
// B vector8B  at: OFF_B + ((wn*4+ks)*8+nt)*256 + (g*4 + (c ^ ((g>>2)&1) ^ ((nt&1)<<1)))*8 + q*4

// ---------------- kernel 0: zero output + counters ----------------
__global__ void k_zero(float* __restrict__ out) {
    int i = blockIdx.x * blockDim.x + threadIdx.x;
    ((float4*)out)[i] = make_float4(0.f, 0.f, 0.f, 0.f);
    if (i < NEXP) g_counts[i] = 0;
}

// ---------------- kernel 1: router (fp32 exact) ----------------
__global__ __launch_bounds__(256) void k_router(const float* __restrict__ x,
                                                const float* __restrict__ rw,
                                                float* __restrict__ logits) {
    __shared__ float4 sx4[256];
    __shared__ float  slog[NEXP];
    const int t = blockIdx.x, tid = threadIdx.x;
    sx4[tid] = ((const float4*)(x + (size_t)t * DMODEL))[tid];
    __syncthreads();
    const int w = tid >> 5, lane = tid & 31;
    const float4* r4 = (const float4*)(rw + (size_t)w * DMODEL);
    float s = 0.f;
#pragma unroll
    for (int j = 0; j < 8; j++) {
        float4 a = sx4[lane + j * 32];
        float4 b = r4[lane + j * 32];
        s += a.x * b.x + a.y * b.y + a.z * b.z + a.w * b.w;
    }
#pragma unroll
    for (int o = 16; o; o >>= 1) s += __shfl_xor_sync(0xffffffffu, s, o);
    if (lane == 0) { slog[w] = s; logits[t * NEXP + w] = s; }
    __syncthreads();
    if (tid == 0) {
        float v0 = -INFINITY, v1 = -INFINITY; int i0 = 0, i1 = 0;
#pragma unroll
        for (int e = 0; e < NEXP; e++) { float v = slog[e]; if (v > v0) { v0 = v; i0 = e; } }
#pragma unroll
        for (int e = 0; e < NEXP; e++) { if (e == i0) continue; float v = slog[e]; if (v > v1) { v1 = v; i1 = e; } }
        float ex = expf(v1 - v0);
        float inv = 1.f / (1.f + ex);
        int p0 = atomicAdd(&g_counts[i0], 1);
        g_elist[i0][p0] = t; g_egate[i0][p0] = inv;
        int p1 = atomicAdd(&g_counts[i1], 1);
        g_elist[i1][p1] = t; g_egate[i1][p1] = ex * inv;
    }
}

// ---------------- shared GEMM machinery (block 128x256, warp 64x64) ----------
struct GemmCtx {
    // producer A: r = tid>>1, hA = tid&1 (16 floats); producer B: n = tid (32 floats)
    int r, hA, wmr, mtr, subr, gr;     // A store coords
    int n, wnr, ntr, gn;               // B store coords
    int wm, wn, g, c;                  // consumer coords
    uint32_t aoff, boff0, boff1;       // consumer lane offsets
};

__device__ __forceinline__ void ctx_init(GemmCtx& X, int tid) {
    X.r = tid >> 1; X.hA = tid & 1;
    X.wmr = X.r >> 6; X.mtr = (X.r >> 4) & 3; X.subr = (X.r >> 3) & 1; X.gr = X.r & 7;
    X.n = tid; X.wnr = X.n >> 6; X.ntr = (X.n >> 3) & 7; X.gn = X.n & 7;
    const int wid = tid >> 5, lane = tid & 31;
    X.wm = wid >> 2; X.wn = wid & 3; X.g = lane >> 2; X.c = lane & 3;
    X.aoff  = (X.g * 4 + (X.c ^ ((X.g >> 1) & 3))) * 16;
    X.boff0 = (X.g * 4 + (X.c ^ ((X.g >> 2) & 1))) * 8;
    X.boff1 = (X.g * 4 + (X.c ^ ((X.g >> 2) & 1) ^ 2)) * 8;
}

__device__ __forceinline__ void store_frags(char* smem, const GemmCtx& X,
                                            const float4* rA4, const float4* rB4) {
    // A: 16 elems -> fragment-major
#pragma unroll
    for (int j = 0; j < 2; j++) {
        const int ks = 2 * X.hA + j;
        char* blk = smem + OFF_A + (((X.wmr * 4 + ks) * 4 + X.mtr) << 9);
#pragma unroll
        for (int q = 0; q < 2; q++) {
            float4 v = rA4[j * 2 + q];
            const float vv[4] = { v.x, v.y, v.z, v.w };
#pragma unroll
            for (int c = 0; c < 4; c++)
                *(uint32_t*)(blk + ((X.gr * 4 + (c ^ ((X.gr >> 1) & 3))) << 4)
                             + ((X.subr + 2 * q) << 2)) = f2tf(vv[c]);
        }
    }
    // B: 32 elems
#pragma unroll
    for (int ks = 0; ks < 4; ks++) {
        char* blk = smem + OFF_B + (((X.wnr * 4 + ks) * 8 + X.ntr) << 8);
        const int sw = ((X.gn >> 2) & 1) ^ ((X.ntr & 1) << 1);
#pragma unroll
        for (int q = 0; q < 2; q++) {
            float4 v = rB4[ks * 2 + q];
            const float vv[4] = { v.x, v.y, v.z, v.w };
#pragma unroll
            for (int c = 0; c < 4; c++)
                *(uint32_t*)(blk + ((X.gn * 4 + (c ^ sw)) << 3) + (q << 2)) = f2tf(vv[c]);
        }
    }
}

__device__ __forceinline__ void mma_chunk(const char* smem, const GemmCtx& X,
                                          float acc[4][8][4]) {
#pragma unroll
    for (int ks = 0; ks < 4; ks++) {
        uint4 af[4];
        uint2 bf[8];
#pragma unroll
        for (int mt = 0; mt < 4; mt++)
            af[mt] = *(const uint4*)(smem + OFF_A + (((X.wm * 4 + ks) * 4 + mt) << 9) + X.aoff);
#pragma unroll
        for (int nt = 0; nt < 8; nt++)
            bf[nt] = *(const uint2*)(smem + OFF_B + (((X.wn * 4 + ks) * 8 + nt) << 8)
                                     + ((nt & 1) ? X.boff1 : X.boff0));
#pragma unroll
        for (int mt = 0; mt < 4; mt++)
#pragma unroll
            for (int nt = 0; nt < 8; nt++)
                mma8(acc[mt][nt], (const uint32_t*)&af[mt], (const uint32_t*)&bf[nt]);
    }
}

// ---------------- kernel 2: grouped GEMM1 + SwiGLU ----------------
// N=256 tile cols interleave (h1,h2): col j -> w_in row (j even: f0+j/2, odd: DFF+f0+j/2)
__global__ __launch_bounds__(256, 1)
void k_gemm1(const float* __restrict__ x, const float* __restrict__ w_in) {
    extern __shared__ char smem[];
    const int e   = blockIdx.z;
    const int cnt = g_counts[e];
    const int m0  = blockIdx.y * 128;
    if (m0 >= cnt) return;
    const int valid = min(128, cnt - m0);
    const int f0 = blockIdx.x * 128;

    const int tid = threadIdx.x;
    GemmCtx X; ctx_init(X, tid);
    int* tok = (int*)(smem + OFF_TOK);

    if (tid < 128) tok[tid] = g_elist[e][m0 + min(tid, valid - 1)];
    __syncthreads();

    const float* aptr = x + (size_t)tok[X.r] * DMODEL + X.hA * 16;
    const int wrow = (X.n & 1) ? (DFF + f0 + (X.n >> 1)) : (f0 + (X.n >> 1));
    const float* bptr = w_in + (size_t)e * (2 * DFF) * DMODEL + (size_t)wrow * DMODEL;

    float acc[4][8][4];
#pragma unroll
    for (int a = 0; a < 4; a++)
#pragma unroll
        for (int b = 0; b < 8; b++)
#pragma unroll
            for (int q = 0; q < 4; q++) acc[a][b][q] = 0.f;

    float4 rA4[4], rB4[8];
#pragma unroll
    for (int f = 0; f < 4; f++) rA4[f] = *(const float4*)(aptr + f * 4);
#pragma unroll
    for (int u = 0; u < 8; u++) rB4[u] = *(const float4*)(bptr + u * 4);

    const int NC = DMODEL / KCH;  // 32
    for (int ic = 0; ic < NC; ic++) {
        __syncthreads();
        store_frags(smem, X, rA4, rB4);
        __syncthreads();
        if (ic + 1 < NC) {
            const int k0 = (ic + 1) * KCH;
#pragma unroll
            for (int f = 0; f < 4; f++) rA4[f] = *(const float4*)(aptr + k0 + f * 4);
#pragma unroll
            for (int u = 0; u < 8; u++) rB4[u] = *(const float4*)(bptr + k0 + u * 4);
        }
        mma_chunk(smem, X, acc);
    }

    // SwiGLU epilogue: thread cols 2c,2c+1 = (h1,h2) of pair p = wn*32+nt*4+c
    float* abase = g_act + ((size_t)e * T_TOKENS + m0) * DFF + f0;
#pragma unroll
    for (int mt = 0; mt < 4; mt++) {
        const int R = X.wm * 64 + mt * 16 + X.g;
        float* d0 = abase + (size_t)R * DFF;
#pragma unroll
        for (int nt = 0; nt < 8; nt++) {
            const int p = X.wn * 32 + nt * 4 + X.c;
            if (R < valid) {
                float a = acc[mt][nt][0], h = acc[mt][nt][1];
                d0[p] = (a / (1.f + expf(-a))) * h;
            }
            if (R + 8 < valid) {
                float a = acc[mt][nt][2], h = acc[mt][nt][3];
                d0[p + (size_t)8 * DFF] = (a / (1.f + expf(-a))) * h;
            }
        }
    }
}

// ---------------- kernel 3: grouped GEMM2 + gated scatter-add ----------------
__global__ __launch_bounds__(256, 1)
void k_gemm2(const float* __restrict__ w_out, float* __restrict__ out) {
    extern __shared__ char smem[];
    const int e   = blockIdx.z;
    const int cnt = g_counts[e];
    const int m0  = blockIdx.y * 128;
    if (m0 >= cnt) return;
    const int valid = min(128, cnt - m0);
    const int n0 = blockIdx.x * 256;

    const int tid = threadIdx.x;
    GemmCtx X; ctx_init(X, tid);
    int*   tok  = (int*)(smem + OFF_TOK);
    float* gate = (float*)(smem + OFF_GATE);

    if (tid < 128) {
        int i = m0 + min(tid, valid - 1);
        tok[tid]  = g_elist[e][i];
        gate[tid] = g_egate[e][i];
    }
    __syncthreads();

    const float* aptr = g_act + ((size_t)e * T_TOKENS + m0 + min(X.r, valid - 1)) * DFF + X.hA * 16;
    const float* bptr = w_out + (size_t)e * DMODEL * DFF + (size_t)(n0 + X.n) * DFF;

    float acc[4][8][4];
#pragma unroll
    for (int a = 0; a < 4; a++)
#pragma unroll
        for (int b = 0; b < 8; b++)
#pragma unroll
            for (int q = 0; q < 4; q++) acc[a][b][q] = 0.f;

    float4 rA4[4], rB4[8];
#pragma unroll
    for (int f = 0; f < 4; f++) rA4[f] = *(const float4*)(aptr + f * 4);
#pragma unroll
    for (int u = 0; u < 8; u++) rB4[u] = *(const float4*)(bptr + u * 4);

    const int NC = DFF / KCH;  // 64
    for (int ic = 0; ic < NC; ic++) {
        __syncthreads();
        store_frags(smem, X, rA4, rB4);
        __syncthreads();
        if (ic + 1 < NC) {
            const int k0 = (ic + 1) * KCH;
#pragma unroll
            for (int f = 0; f < 4; f++) rA4[f] = *(const float4*)(aptr + k0 + f * 4);
#pragma unroll
            for (int u = 0; u < 8; u++) rB4[u] = *(const float4*)(bptr + k0 + u * 4);
        }
        mma_chunk(smem, X, acc);
    }

    // gated atomic scatter (each token exactly 2 contributions -> deterministic)
#pragma unroll
    for (int mt = 0; mt < 4; mt++) {
        const int R = X.wm * 64 + mt * 16 + X.g;
        const int tk0 = tok[R];     const float gt0 = gate[R];
        const int tk1 = tok[R + 8]; const float gt1 = gate[R + 8];
        float* o0 = out + (size_t)tk0 * DMODEL + n0;
        float* o1 = out + (size_t)tk1 * DMODEL + n0;
#pragma unroll
        for (int nt = 0; nt < 8; nt++) {
            const int col = X.wn * 64 + nt * 8 + 2 * X.c;
            if (R < valid) {
                atomicAdd(o0 + col,     gt0 * acc[mt][nt][0]);
                atomicAdd(o0 + col + 1, gt0 * acc[mt][nt][1]);
            }
            if (R + 8 < valid) {
                atomicAdd(o1 + col,     gt1 * acc[mt][nt][2]);
                atomicAdd(o1 + col + 1, gt1 * acc[mt][nt][3]);
            }
        }
    }
}

// ---------------- launch ----------------
extern "C" void kernel_launch(void* const* d_in, const int* in_sizes, int n_in,
                              void* d_out, int out_size) {
    const float* x     = (const float*)d_in[0];
    const float* rw    = (const float*)d_in[1];
    const float* w_in  = (const float*)d_in[2];
    const float* w_out = (const float*)d_in[3];
    float* out    = (float*)d_out;
    float* logits = out + (size_t)T_TOKENS * DMODEL;

    static int attr_done = 0;
    if (!attr_done) {
        cudaFuncSetAttribute(k_gemm1, cudaFuncAttributeMaxDynamicSharedMemorySize, SMEM_SZ);
        cudaFuncSetAttribute(k_gemm2, cudaFuncAttributeMaxDynamicSharedMemorySize, SMEM_SZ);
        attr_done = 1;
    }

    k_zero<<<(T_TOKENS * DMODEL / 4) / 256, 256>>>(out);
    k_router<<<T_TOKENS, 256>>>(x, rw, logits);
    k_gemm1<<<dim3(DFF / 128, T_TOKENS / 128, NEXP), 256, SMEM_SZ>>>(x, w_in);
    k_gemm2<<<dim3(DMODEL / 256, T_TOKENS / 128, NEXP), 256, SMEM_SZ>>>(w_out, out);
}

// round 4
// speedup vs baseline: 1.0380x; 1.0380x over previous
#include <cuda_runtime.h>
#include <cstdint>
#include <math.h>

#define T_TOKENS 4096
#define DMODEL   1024
#define DFF      2048
#define NEXP     8
#define KCH      32

// smem: A 128x128B | B 256x128B | tok | gate
#define OFF_A    0
#define OFF_B    16384
#define OFF_TOK  49152
#define OFF_GATE 49664
#define SMEM_SZ  50176

// ---------------- scratch ----------------
__device__ int   g_counts[NEXP];
__device__ int   g_elist[NEXP][T_TOKENS];
__device__ float g_egate[NEXP][T_TOKENS];
__device__ float g_act[(size_t)NEXP * T_TOKENS * DFF];   // never-written slots stay 0

// ---------------- helpers ----------------
__device__ __forceinline__ uint32_t smem_u32(const void* p) {
    uint32_t a;
    asm("{ .reg .u64 t; cvta.to.shared.u64 t, %1; cvt.u32.u64 %0, t; }" : "=r"(a) : "l"(p));
    return a;
}
__device__ __forceinline__ uint32_t f2tf(float x) {
    uint32_t r; asm("cvt.rna.tf32.f32 %0, %1;" : "=r"(r) : "f"(x)); return r;
}
__device__ __forceinline__ void sts128(uint32_t addr, uint32_t a, uint32_t b, uint32_t c, uint32_t d) {
    asm volatile("st.shared.v4.b32 [%0], {%1,%2,%3,%4};" :: "r"(addr), "r"(a), "r"(b), "r"(c), "r"(d));
}
__device__ __forceinline__ void ldsm4(uint4& r, uint32_t addr) {
    asm volatile("ldmatrix.sync.aligned.m8n8.x4.shared.b16 {%0,%1,%2,%3}, [%4];"
                 : "=r"(r.x), "=r"(r.y), "=r"(r.z), "=r"(r.w) : "r"(addr));
}
__device__ __forceinline__ void mma8(float* d, const uint32_t* a, uint32_t b0, uint32_t b1) {
    asm volatile(
        "mma.sync.aligned.m16n8k8.row.col.f32.tf32.tf32.f32 "
        "{%0,%1,%2,%3}, {%4,%5,%6,%7}, {%8,%9}, {%0,%1,%2,%3};\n"
        : "+f"(d[0]), "+f"(d[1]), "+f"(d[2]), "+f"(d[3])
        : "r"(a[0]), "r"(a[1]), "r"(a[2]), "r"(a[3]), "r"(b0), "r"(b1));
}

// ---------------- kernel 0: zero output + counters ----------------
__global__ void k_zero(float* __restrict__ out) {
    int i = blockIdx.x * blockDim.x + threadIdx.x;
    ((float4*)out)[i] = make_float4(0.f, 0.f, 0.f, 0.f);
    if (i < NEXP) g_counts[i] = 0;
}

// ---------------- kernel 1: router (fp32 exact) ----------------
__global__ __launch_bounds__(256) void k_router(const float* __restrict__ x,
                                                const float* __restrict__ rw,
                                                float* __restrict__ logits) {
    __shared__ float4 sx4[256];
    __shared__ float  slog[NEXP];
    const int t = blockIdx.x, tid = threadIdx.x;
    sx4[tid] = ((const float4*)(x + (size_t)t * DMODEL))[tid];
    __syncthreads();
    const int w = tid >> 5, lane = tid & 31;
    const float4* r4 = (const float4*)(rw + (size_t)w * DMODEL);
    float s = 0.f;
#pragma unroll
    for (int j = 0; j < 8; j++) {
        float4 a = sx4[lane + j * 32];
        float4 b = r4[lane + j * 32];
        s += a.x * b.x + a.y * b.y + a.z * b.z + a.w * b.w;
    }
#pragma unroll
    for (int o = 16; o; o >>= 1) s += __shfl_xor_sync(0xffffffffu, s, o);
    if (lane == 0) { slog[w] = s; logits[t * NEXP + w] = s; }
    __syncthreads();
    if (tid == 0) {
        float v0 = -INFINITY, v1 = -INFINITY; int i0 = 0, i1 = 0;
#pragma unroll
        for (int e = 0; e < NEXP; e++) { float v = slog[e]; if (v > v0) { v0 = v; i0 = e; } }
#pragma unroll
        for (int e = 0; e < NEXP; e++) { if (e == i0) continue; float v = slog[e]; if (v > v1) { v1 = v; i1 = e; } }
        float ex = expf(v1 - v0);
        float inv = 1.f / (1.f + ex);
        int p0 = atomicAdd(&g_counts[i0], 1);
        g_elist[i0][p0] = t; g_egate[i0][p0] = inv;
        int p1 = atomicAdd(&g_counts[i1], 1);
        g_elist[i1][p1] = t; g_egate[i1][p1] = ex * inv;
    }
}

// ---------------- GEMM context (block 128x256, warp 64x64, ldmatrix) --------
struct Ctx {
    // producer
    uint32_t aSt[4], bSt[8];
    int rowA, hA;
    // consumer
    uint32_t a_base[4], b_base[4], swA[4], swB[4];
    int wm, wn, g, c;
};

__device__ __forceinline__ void ctx_init(Ctx& X, int tid, uint32_t sbase) {
    const int lane = tid & 31, wid = tid >> 5;
    X.wm = wid >> 2; X.wn = wid & 3; X.g = lane >> 2; X.c = lane & 3;
    // producer A: row = tid>>1, 64B half = tid&1
    X.rowA = tid >> 1; X.hA = tid & 1;
#pragma unroll
    for (int q = 0; q < 4; q++)
        X.aSt[q] = sbase + OFF_A + X.rowA * 128 + (((X.hA * 4 + q) ^ (X.rowA & 7)) << 4);
#pragma unroll
    for (int q = 0; q < 8; q++)
        X.bSt[q] = sbase + OFF_B + tid * 128 + ((q ^ (tid & 7)) << 4);
    // consumer ldmatrix bases
    const int arow = X.wm * 64 + (lane & 15);
    const int auhi = lane >> 4;
#pragma unroll
    for (int mt = 0; mt < 4; mt++)
        X.a_base[mt] = sbase + OFF_A + (arow + mt * 16) * 128;
    const int brow = X.wn * 64 + (lane & 7) + ((lane & 16) >> 1);
    const int bpar = (lane >> 3) & 1;
#pragma unroll
    for (int nt2 = 0; nt2 < 4; nt2++)
        X.b_base[nt2] = sbase + OFF_B + (brow + nt2 * 16) * 128;
#pragma unroll
    for (int ks = 0; ks < 4; ks++) {
        X.swA[ks] = (uint32_t)(((ks * 2 + auhi) ^ (lane & 7)) << 4);
        X.swB[ks] = (uint32_t)(((ks * 2 + bpar) ^ (lane & 7)) << 4);
    }
}

__device__ __forceinline__ void store_chunk(const Ctx& X, const float4* rA4, const float4* rB4) {
#pragma unroll
    for (int q = 0; q < 4; q++) {
        float4 v = rA4[q];
        sts128(X.aSt[q], f2tf(v.x), f2tf(v.y), f2tf(v.z), f2tf(v.w));
    }
#pragma unroll
    for (int q = 0; q < 8; q++) {
        float4 v = rB4[q];
        sts128(X.bSt[q], f2tf(v.x), f2tf(v.y), f2tf(v.z), f2tf(v.w));
    }
}

__device__ __forceinline__ void mma_chunk(const Ctx& X, float acc[4][8][4]) {
#pragma unroll
    for (int ks = 0; ks < 4; ks++) {
        uint4 af[4], bf[4];
#pragma unroll
        for (int mt = 0; mt < 4; mt++) ldsm4(af[mt], X.a_base[mt] + X.swA[ks]);
#pragma unroll
        for (int nt2 = 0; nt2 < 4; nt2++) ldsm4(bf[nt2], X.b_base[nt2] + X.swB[ks]);
#pragma unroll
        for (int mt = 0; mt < 4; mt++)
#pragma unroll
            for (int nt2 = 0; nt2 < 4; nt2++) {
                mma8(acc[mt][2 * nt2],     (const uint32_t*)&af[mt], bf[nt2].x, bf[nt2].y);
                mma8(acc[mt][2 * nt2 + 1], (const uint32_t*)&af[mt], bf[nt2].z, bf[nt2].w);
            }
    }
}

// ---------------- kernel 2: grouped GEMM1 + SwiGLU ----------------
// N=256 tile cols interleave (h1,h2): col j -> w_in row (j even: f0+j/2, odd: DFF+f0+j/2)
__global__ __launch_bounds__(256, 1)
void k_gemm1(const float* __restrict__ x, const float* __restrict__ w_in) {
    extern __shared__ char smem[];
    const int e   = blockIdx.z;
    const int cnt = g_counts[e];
    const int m0  = blockIdx.y * 128;
    if (m0 >= cnt) return;
    const int valid = min(128, cnt - m0);
    const int f0 = blockIdx.x * 128;

    const int tid = threadIdx.x;
    const uint32_t sbase = smem_u32(smem);
    Ctx X; ctx_init(X, tid, sbase);
    int* tok = (int*)(smem + OFF_TOK);

    if (tid < 128) tok[tid] = g_elist[e][m0 + min(tid, valid - 1)];
    __syncthreads();

    const float* aptr = x + (size_t)tok[X.rowA] * DMODEL + X.hA * 16;
    const int nC = tid;
    const int wrow = (nC & 1) ? (DFF + f0 + (nC >> 1)) : (f0 + (nC >> 1));
    const float* bptr = w_in + (size_t)e * (2 * DFF) * DMODEL + (size_t)wrow * DMODEL;

    float acc[4][8][4];
#pragma unroll
    for (int a = 0; a < 4; a++)
#pragma unroll
        for (int b = 0; b < 8; b++)
#pragma unroll
            for (int q = 0; q < 4; q++) acc[a][b][q] = 0.f;

    float4 rA4[4], rB4[8];
#pragma unroll
    for (int q = 0; q < 4; q++) rA4[q] = *(const float4*)(aptr + q * 4);
#pragma unroll
    for (int q = 0; q < 8; q++) rB4[q] = *(const float4*)(bptr + q * 4);

    const int NC = DMODEL / KCH;  // 32
    for (int ic = 0; ic < NC; ic++) {
        __syncthreads();
        store_chunk(X, rA4, rB4);
        __syncthreads();
        if (ic + 1 < NC) {
            const int k0 = (ic + 1) * KCH;
#pragma unroll
            for (int q = 0; q < 4; q++) rA4[q] = *(const float4*)(aptr + k0 + q * 4);
#pragma unroll
            for (int q = 0; q < 8; q++) rB4[q] = *(const float4*)(bptr + k0 + q * 4);
        }
        mma_chunk(X, acc);
    }

    // SwiGLU epilogue: thread cols (2c,2c+1) = (h1,h2), pair p = wn*32+nt*4+c
    float* abase = g_act + ((size_t)e * T_TOKENS + m0) * DFF + f0;
#pragma unroll
    for (int mt = 0; mt < 4; mt++) {
        const int R = X.wm * 64 + mt * 16 + X.g;
        float* d0 = abase + (size_t)R * DFF;
#pragma unroll
        for (int nt = 0; nt < 8; nt++) {
            const int p = X.wn * 32 + nt * 4 + X.c;
            if (R < valid) {
                float a = acc[mt][nt][0], h = acc[mt][nt][1];
                d0[p] = (a / (1.f + expf(-a))) * h;
            }
            if (R + 8 < valid) {
                float a = acc[mt][nt][2], h = acc[mt][nt][3];
                d0[p + (size_t)8 * DFF] = (a / (1.f + expf(-a))) * h;
            }
        }
    }
}

// ---------------- kernel 3: grouped GEMM2 + gated scatter-add ----------------
__global__ __launch_bounds__(256, 1)
void k_gemm2(const float* __restrict__ w_out, float* __restrict__ out) {
    extern __shared__ char smem[];
    const int e   = blockIdx.z;
    const int cnt = g_counts[e];
    const int m0  = blockIdx.y * 128;
    if (m0 >= cnt) return;
    const int valid = min(128, cnt - m0);
    const int n0 = blockIdx.x * 256;

    const int tid = threadIdx.x;
    const uint32_t sbase = smem_u32(smem);
    Ctx X; ctx_init(X, tid, sbase);
    int*   tok  = (int*)(smem + OFF_TOK);
    float* gate = (float*)(smem + OFF_GATE);

    if (tid < 128) {
        int i = m0 + min(tid, valid - 1);
        tok[tid]  = g_elist[e][i];
        gate[tid] = g_egate[e][i];
    }
    __syncthreads();

    // rows >= valid read never-written g_act slots (zeros) -> results discarded
    const float* aptr = g_act + ((size_t)e * T_TOKENS + m0 + X.rowA) * DFF + X.hA * 16;
    const float* bptr = w_out + (size_t)e * DMODEL * DFF + (size_t)(n0 + tid) * DFF;

    float acc[4][8][4];
#pragma unroll
    for (int a = 0; a < 4; a++)
#pragma unroll
        for (int b = 0; b < 8; b++)
#pragma unroll
            for (int q = 0; q < 4; q++) acc[a][b][q] = 0.f;

    float4 rA4[4], rB4[8];
#pragma unroll
    for (int q = 0; q < 4; q++) rA4[q] = *(const float4*)(aptr + q * 4);
#pragma unroll
    for (int q = 0; q < 8; q++) rB4[q] = *(const float4*)(bptr + q * 4);

    const int NC = DFF / KCH;  // 64
    for (int ic = 0; ic < NC; ic++) {
        __syncthreads();
        store_chunk(X, rA4, rB4);
        __syncthreads();
        if (ic + 1 < NC) {
            const int k0 = (ic + 1) * KCH;
#pragma unroll
            for (int q = 0; q < 4; q++) rA4[q] = *(const float4*)(aptr + k0 + q * 4);
#pragma unroll
            for (int q = 0; q < 8; q++) rB4[q] = *(const float4*)(bptr + k0 + q * 4);
        }
        mma_chunk(X, acc);
    }

    // gated atomic scatter (each token exactly 2 contributions -> deterministic)
#pragma unroll
    for (int mt = 0; mt < 4; mt++) {
        const int R = X.wm * 64 + mt * 16 + X.g;
        const int tk0 = tok[R];     const float gt0 = gate[R];
        const int tk1 = tok[R + 8]; const float gt1 = gate[R + 8];
        float* o0 = out + (size_t)tk0 * DMODEL + n0;
        float* o1 = out + (size_t)tk1 * DMODEL + n0;
#pragma unroll
        for (int nt = 0; nt < 8; nt++) {
            const int col = X.wn * 64 + nt * 8 + 2 * X.c;
            if (R < valid) {
                atomicAdd(o0 + col,     gt0 * acc[mt][nt][0]);
                atomicAdd(o0 + col + 1, gt0 * acc[mt][nt][1]);
            }
            if (R + 8 < valid) {
                atomicAdd(o1 + col,     gt1 * acc[mt][nt][2]);
                atomicAdd(o1 + col + 1, gt1 * acc[mt][nt][3]);
            }
        }
    }
}

// ---------------- launch ----------------
extern "C" void kernel_launch(void* const* d_in, const int* in_sizes, int n_in,
                              void* d_out, int out_size) {
    const float* x     = (const float*)d_in[0];
    const float* rw    = (const float*)d_in[1];
    const float* w_in  = (const float*)d_in[2];
    const float* w_out = (const float*)d_in[3];
    float* out    = (float*)d_out;
    float* logits = out + (size_t)T_TOKENS * DMODEL;

    static int attr_done = 0;
    if (!attr_done) {
        cudaFuncSetAttribute(k_gemm1, cudaFuncAttributeMaxDynamicSharedMemorySize, SMEM_SZ);
        cudaFuncSetAttribute(k_gemm2, cudaFuncAttributeMaxDynamicSharedMemorySize, SMEM_SZ);
        attr_done = 1;
    }

    k_zero<<<(T_TOKENS * DMODEL / 4) / 256, 256>>>(out);
    k_router<<<T_TOKENS, 256>>>(x, rw, logits);
    k_gemm1<<<dim3(DFF / 128, T_TOKENS / 128, NEXP), 256, SMEM_SZ>>>(x, w_in);
    k_gemm2<<<dim3(DMODEL / 256, T_TOKENS / 128, NEXP), 256, SMEM_SZ>>>(w_out, out);
}

// round 5
// speedup vs baseline: 2.0320x; 1.9575x over previous
#include <cuda_runtime.h>
#include <cuda_fp16.h>
#include <cstdint>
#include <math.h>

#define T_TOKENS 4096
#define DMODEL   1024
#define DFF      2048
#define NEXP     8
#define KCH      64          // fp16 chunk: 128B rows

// smem: 3 stages of (A 16KB | B 32KB) + meta
#define STAGE    49152
#define OFF_B    16384
#define OFF_META 147456
#define SMEM_SZ  148480

// ---------------- scratch (device globals) ----------------
__device__ int    g_counts[NEXP];
__device__ int    g_elist[NEXP][T_TOKENS];
__device__ float  g_egate[NEXP][T_TOKENS];
__device__ __half g_x16[(size_t)T_TOKENS * DMODEL];
__device__ __half g_win16[(size_t)NEXP * 2 * DFF * DMODEL];
__device__ __half g_wout16[(size_t)NEXP * DMODEL * DFF];
__device__ __half g_act16[(size_t)NEXP * T_TOKENS * DFF];   // unwritten slots stay 0

// ---------------- asm helpers ----------------
__device__ __forceinline__ uint32_t smem_u32(const void* p) {
    uint32_t a;
    asm("{ .reg .u64 t; cvta.to.shared.u64 t, %1; cvt.u32.u64 %0, t; }" : "=r"(a) : "l"(p));
    return a;
}
__device__ __forceinline__ void cpa16(uint32_t dst, const void* src) {
    asm volatile("cp.async.cg.shared.global [%0], [%1], 16;" :: "r"(dst), "l"(src));
}
#define CP_COMMIT() asm volatile("cp.async.commit_group;" ::: "memory")
#define CP_WAIT1()  asm volatile("cp.async.wait_group 1;" ::: "memory")
__device__ __forceinline__ void ldsm4(uint4& r, uint32_t addr) {
    asm volatile("ldmatrix.sync.aligned.m8n8.x4.shared.b16 {%0,%1,%2,%3}, [%4];"
                 : "=r"(r.x), "=r"(r.y), "=r"(r.z), "=r"(r.w) : "r"(addr));
}
__device__ __forceinline__ void mma16(float* d, const uint4& a, uint32_t b0, uint32_t b1) {
    asm volatile(
        "mma.sync.aligned.m16n8k16.row.col.f32.f16.f16.f32 "
        "{%0,%1,%2,%3}, {%4,%5,%6,%7}, {%8,%9}, {%0,%1,%2,%3};\n"
        : "+f"(d[0]), "+f"(d[1]), "+f"(d[2]), "+f"(d[3])
        : "r"(a.x), "r"(a.y), "r"(a.z), "r"(a.w), "r"(b0), "r"(b1));
}

// ---------------- kernel: fp32 -> fp16 convert ----------------
__global__ void k_cvt(const float4* __restrict__ src, uint2* __restrict__ dst, int n4) {
    int i = blockIdx.x * blockDim.x + threadIdx.x;
    if (i >= n4) return;
    float4 v = src[i];
    __half2 h0 = __floats2half2_rn(v.x, v.y);
    __half2 h1 = __floats2half2_rn(v.z, v.w);
    dst[i] = make_uint2(*(uint32_t*)&h0, *(uint32_t*)&h1);
}

// ---------------- kernel 0: zero output + counters ----------------
__global__ void k_zero(float* __restrict__ out) {
    int i = blockIdx.x * blockDim.x + threadIdx.x;
    ((float4*)out)[i] = make_float4(0.f, 0.f, 0.f, 0.f);
    if (i < NEXP) g_counts[i] = 0;
}

// ---------------- kernel 1: router (fp32 exact) ----------------
__global__ __launch_bounds__(256) void k_router(const float* __restrict__ x,
                                                const float* __restrict__ rw,
                                                float* __restrict__ logits) {
    __shared__ float4 sx4[256];
    __shared__ float  slog[NEXP];
    const int t = blockIdx.x, tid = threadIdx.x;
    sx4[tid] = ((const float4*)(x + (size_t)t * DMODEL))[tid];
    __syncthreads();
    const int w = tid >> 5, lane = tid & 31;
    const float4* r4 = (const float4*)(rw + (size_t)w * DMODEL);
    float s = 0.f;
#pragma unroll
    for (int j = 0; j < 8; j++) {
        float4 a = sx4[lane + j * 32];
        float4 b = r4[lane + j * 32];
        s += a.x * b.x + a.y * b.y + a.z * b.z + a.w * b.w;
    }
#pragma unroll
    for (int o = 16; o; o >>= 1) s += __shfl_xor_sync(0xffffffffu, s, o);
    if (lane == 0) { slog[w] = s; logits[t * NEXP + w] = s; }
    __syncthreads();
    if (tid == 0) {
        float v0 = -INFINITY, v1 = -INFINITY; int i0 = 0, i1 = 0;
#pragma unroll
        for (int e = 0; e < NEXP; e++) { float v = slog[e]; if (v > v0) { v0 = v; i0 = e; } }
#pragma unroll
        for (int e = 0; e < NEXP; e++) { if (e == i0) continue; float v = slog[e]; if (v > v1) { v1 = v; i1 = e; } }
        float ex = expf(v1 - v0);
        float inv = 1.f / (1.f + ex);
        int p0 = atomicAdd(&g_counts[i0], 1);
        g_elist[i0][p0] = t; g_egate[i0][p0] = inv;
        int p1 = atomicAdd(&g_counts[i1], 1);
        g_elist[i1][p1] = t; g_egate[i1][p1] = ex * inv;
    }
}

// ---------------- GEMM machinery: block 128x256, warp 64x32, 512 thr -------
struct Ctx {
    uint32_t aBase[4], bBase[2], swz[4];   // ldsm (relative to stage base)
    uint32_t aDst[2], bDst[4];             // cp.async dst (relative to stage base)
    int wm, wn, g, c;
    int rA, uA0, rB, uB0;
};

__device__ __forceinline__ void ctx_init(Ctx& X, int tid) {
    const int lane = tid & 31, wid = tid >> 5;
    X.wm = wid >> 3; X.wn = wid & 7; X.g = lane >> 2; X.c = lane & 3;
    const int rl = lane & 15, hi = lane >> 4;
#pragma unroll
    for (int mt = 0; mt < 4; mt++)
        X.aBase[mt] = (uint32_t)((X.wm * 64 + mt * 16 + rl) * 128);
#pragma unroll
    for (int j = 0; j < 2; j++)
        X.bBase[j] = (uint32_t)(OFF_B + (X.wn * 32 + j * 16 + rl) * 128);
#pragma unroll
    for (int ks = 0; ks < 4; ks++)
        X.swz[ks] = (uint32_t)(((ks * 2 + hi) ^ (lane & 7)) << 4);
    // producers: A row = tid>>2 (units 2), B row = tid>>1 (units 4)
    X.rA = tid >> 2; X.uA0 = (tid & 3) * 2;
    X.rB = tid >> 1; X.uB0 = (tid & 1) * 4;
#pragma unroll
    for (int q = 0; q < 2; q++)
        X.aDst[q] = (uint32_t)(X.rA * 128 + (((X.uA0 + q) ^ (X.rA & 7)) << 4));
#pragma unroll
    for (int q = 0; q < 4; q++)
        X.bDst[q] = (uint32_t)(OFF_B + X.rB * 128 + (((X.uB0 + q) ^ (X.rB & 7)) << 4));
}

__device__ __forceinline__ void issue_copies(const Ctx& X, uint32_t sb, int s,
                                             const char* aSrc, const char* bSrc, int k0) {
    const uint32_t so = sb + s * STAGE;
    const char* as = aSrc + k0 * 2 + X.uA0 * 16;
    const char* bs = bSrc + k0 * 2 + X.uB0 * 16;
#pragma unroll
    for (int q = 0; q < 2; q++) cpa16(so + X.aDst[q], as + q * 16);
#pragma unroll
    for (int q = 0; q < 4; q++) cpa16(so + X.bDst[q], bs + q * 16);
}

__device__ __forceinline__ void compute(const Ctx& X, uint32_t sb, int s, float acc[4][4][4]) {
    const uint32_t so = sb + s * STAGE;
#pragma unroll
    for (int ks = 0; ks < 4; ks++) {
        uint4 af[4], bf[2];
#pragma unroll
        for (int mt = 0; mt < 4; mt++) ldsm4(af[mt], so + X.aBase[mt] + X.swz[ks]);
#pragma unroll
        for (int j = 0; j < 2; j++)    ldsm4(bf[j], so + X.bBase[j] + X.swz[ks]);
#pragma unroll
        for (int mt = 0; mt < 4; mt++)
#pragma unroll
            for (int nt = 0; nt < 4; nt++) {
                const uint4& b = bf[nt >> 1];
                if (nt & 1) mma16(acc[mt][nt], af[mt], b.y, b.w);
                else        mma16(acc[mt][nt], af[mt], b.x, b.z);
            }
    }
}

// ---------------- kernel 2: grouped GEMM1 + SwiGLU (fp16 in, fp16 act out) --
// N=256 tile cols interleave (h1,h2): col j -> w_in row (j even: f0+j/2, odd: DFF+f0+j/2)
__global__ __launch_bounds__(512, 1)
void k_gemm1(void) {
    extern __shared__ char smem[];
    const int e   = blockIdx.z;
    const int cnt = g_counts[e];
    const int m0  = blockIdx.y * 128;
    if (m0 >= cnt) return;
    const int valid = min(128, cnt - m0);
    const int f0 = blockIdx.x * 128;   // pair offset

    const int tid = threadIdx.x;
    const uint32_t sb = smem_u32(smem);
    Ctx X; ctx_init(X, tid);
    int* tok = (int*)(smem + OFF_META);

    if (tid < 128) tok[tid] = g_elist[e][m0 + min(tid, valid - 1)];
    __syncthreads();

    const char* aSrc = (const char*)(g_x16 + (size_t)tok[X.rA] * DMODEL);
    const int wrow = (X.rB & 1) ? (DFF + f0 + (X.rB >> 1)) : (f0 + (X.rB >> 1));
    const char* bSrc = (const char*)(g_win16 + (size_t)e * (2 * DFF) * DMODEL + (size_t)wrow * DMODEL);

    float acc[4][4][4];
#pragma unroll
    for (int a = 0; a < 4; a++)
#pragma unroll
        for (int b = 0; b < 4; b++)
#pragma unroll
            for (int q = 0; q < 4; q++) acc[a][b][q] = 0.f;

    const int NC = DMODEL / KCH;   // 16
    issue_copies(X, sb, 0, aSrc, bSrc, 0);  CP_COMMIT();
    issue_copies(X, sb, 1, aSrc, bSrc, KCH); CP_COMMIT();
    for (int ic = 0; ic < NC; ic++) {
        CP_WAIT1();
        __syncthreads();
        if (ic + 2 < NC) issue_copies(X, sb, (ic + 2) % 3, aSrc, bSrc, (ic + 2) * KCH);
        CP_COMMIT();
        compute(X, sb, ic % 3, acc);
    }

    // SwiGLU epilogue -> fp16 act
    __half* abase = g_act16 + ((size_t)e * T_TOKENS + m0) * DFF + f0;
#pragma unroll
    for (int mt = 0; mt < 4; mt++) {
        const int R = X.wm * 64 + mt * 16 + X.g;
        __half* d0 = abase + (size_t)R * DFF;
#pragma unroll
        for (int nt = 0; nt < 4; nt++) {
            const int p = X.wn * 16 + nt * 4 + X.c;
            if (R < valid) {
                float a = acc[mt][nt][0], h = acc[mt][nt][1];
                d0[p] = __float2half_rn((a / (1.f + expf(-a))) * h);
            }
            if (R + 8 < valid) {
                float a = acc[mt][nt][2], h = acc[mt][nt][3];
                d0[p + (size_t)8 * DFF] = __float2half_rn((a / (1.f + expf(-a))) * h);
            }
        }
    }
}

// ---------------- kernel 3: grouped GEMM2 + gated scatter-add ----------------
__global__ __launch_bounds__(512, 1)
void k_gemm2(float* __restrict__ out) {
    extern __shared__ char smem[];
    const int e   = blockIdx.z;
    const int cnt = g_counts[e];
    const int m0  = blockIdx.y * 128;
    if (m0 >= cnt) return;
    const int valid = min(128, cnt - m0);
    const int n0 = blockIdx.x * 256;

    const int tid = threadIdx.x;
    const uint32_t sb = smem_u32(smem);
    Ctx X; ctx_init(X, tid);
    int*   tok  = (int*)(smem + OFF_META);
    float* gate = (float*)(smem + OFF_META + 512);

    if (tid < 128) {
        int i = m0 + min(tid, valid - 1);
        tok[tid]  = g_elist[e][i];
        gate[tid] = g_egate[e][i];
    }
    __syncthreads();

    // rows >= valid read never-written g_act16 slots (zeros); results discarded
    const char* aSrc = (const char*)(g_act16 + ((size_t)e * T_TOKENS + m0 + X.rA) * DFF);
    const char* bSrc = (const char*)(g_wout16 + (size_t)e * DMODEL * DFF + (size_t)(n0 + X.rB) * DFF);

    float acc[4][4][4];
#pragma unroll
    for (int a = 0; a < 4; a++)
#pragma unroll
        for (int b = 0; b < 4; b++)
#pragma unroll
            for (int q = 0; q < 4; q++) acc[a][b][q] = 0.f;

    const int NC = DFF / KCH;   // 32
    issue_copies(X, sb, 0, aSrc, bSrc, 0);  CP_COMMIT();
    issue_copies(X, sb, 1, aSrc, bSrc, KCH); CP_COMMIT();
    for (int ic = 0; ic < NC; ic++) {
        CP_WAIT1();
        __syncthreads();
        if (ic + 2 < NC) issue_copies(X, sb, (ic + 2) % 3, aSrc, bSrc, (ic + 2) * KCH);
        CP_COMMIT();
        compute(X, sb, ic % 3, acc);
    }

    // gated atomic scatter (each token exactly 2 contributions -> deterministic)
#pragma unroll
    for (int mt = 0; mt < 4; mt++) {
        const int R = X.wm * 64 + mt * 16 + X.g;
        const int tk0 = tok[R];     const float gt0 = gate[R];
        const int tk1 = tok[R + 8]; const float gt1 = gate[R + 8];
        float* o0 = out + (size_t)tk0 * DMODEL + n0;
        float* o1 = out + (size_t)tk1 * DMODEL + n0;
#pragma unroll
        for (int nt = 0; nt < 4; nt++) {
            const int col = X.wn * 32 + nt * 8 + 2 * X.c;
            if (R < valid) {
                atomicAdd(o0 + col,     gt0 * acc[mt][nt][0]);
                atomicAdd(o0 + col + 1, gt0 * acc[mt][nt][1]);
            }
            if (R + 8 < valid) {
                atomicAdd(o1 + col,     gt1 * acc[mt][nt][2]);
                atomicAdd(o1 + col + 1, gt1 * acc[mt][nt][3]);
            }
        }
    }
}

// ---------------- launch ----------------
extern "C" void kernel_launch(void* const* d_in, const int* in_sizes, int n_in,
                              void* d_out, int out_size) {
    const float* x     = (const float*)d_in[0];
    const float* rw    = (const float*)d_in[1];
    const float* w_in  = (const float*)d_in[2];
    const float* w_out = (const float*)d_in[3];
    float* out    = (float*)d_out;
    float* logits = out + (size_t)T_TOKENS * DMODEL;

    static int attr_done = 0;
    if (!attr_done) {
        cudaFuncSetAttribute(k_gemm1, cudaFuncAttributeMaxDynamicSharedMemorySize, SMEM_SZ);
        cudaFuncSetAttribute(k_gemm2, cudaFuncAttributeMaxDynamicSharedMemorySize, SMEM_SZ);
        attr_done = 1;
    }

    uint2* dx16 = nullptr; uint2* dw1 = nullptr; uint2* dw2 = nullptr;
    cudaGetSymbolAddress((void**)&dx16, g_x16);
    cudaGetSymbolAddress((void**)&dw1,  g_win16);
    cudaGetSymbolAddress((void**)&dw2,  g_wout16);

    const int nx = T_TOKENS * DMODEL / 4;
    const int n1 = NEXP * 2 * DFF * DMODEL / 4;
    const int n2 = NEXP * DMODEL * DFF / 4;

    k_zero<<<(T_TOKENS * DMODEL / 4) / 256, 256>>>(out);
    k_cvt<<<(nx + 255) / 256, 256>>>((const float4*)x, dx16, nx);
    k_cvt<<<(n1 + 255) / 256, 256>>>((const float4*)w_in, dw1, n1);
    k_cvt<<<(n2 + 255) / 256, 256>>>((const float4*)w_out, dw2, n2);
    k_router<<<T_TOKENS, 256>>>(x, rw, logits);
    k_gemm1<<<dim3(DFF / 128, T_TOKENS / 128, NEXP), 512, SMEM_SZ>>>();
    k_gemm2<<<dim3(DMODEL / 256, T_TOKENS / 128, NEXP), 512, SMEM_SZ>>>(out);
}